// round 15
// baseline (speedup 1.0000x reference)
#include <cuda_runtime.h>
#include <cuda_bf16.h>
#include <cstdint>

#define H 128
#define MAXN 50000
#define MAXE 800000
#define BN_EPS 1e-5f

// ---------------- device scratch ---------------------------------------------
__device__ float g_t[MAXN * H];
__device__ float g_agg[MAXN * H];
// Fragment slots: 1:Bz0 2:Cc0 3:Bz1 4:Cc1 5:Bz2
__device__ uint4 g_Wfrag[6 * 16 * 8 * 32];
__device__ float g_bf[6 * H];
// fp32 fold scratch
__device__ float g_scr[6 * H * H];
__device__ float g_SL[2 * H * H];
__device__ float g_bfold[2 * H];
__device__ float g_rov[H];
__device__ float g_roc[1];
__device__ float g_T0[100 * H];       // relu(embed_table @ SL0 + bfold0)
// CSR scratch
__device__ int g_cnt[MAXN];
__device__ int g_tmp[MAXN];
__device__ int g_rowptr[MAXN + 1];
__device__ int g_csr_src[MAXE];
__device__ int g_csr_x[MAXE];
__device__ int g_bsum[64];

// ---------------- helpers -------------------------------------------------------
__device__ __forceinline__ uint32_t smem_addr_u32(const void* p) {
    uint32_t a;
    asm("{ .reg .u64 t; cvta.to.shared.u64 t, %1; cvt.u32.u64 %0, t; }" : "=r"(a) : "l"(p));
    return a;
}
__device__ __forceinline__ uint32_t pack_bf16x2(float a, float b) {
    uint32_t ua = (uint32_t)__bfloat16_as_ushort(__float2bfloat16_rn(a));
    uint32_t ub = (uint32_t)__bfloat16_as_ushort(__float2bfloat16_rn(b));
    return ua | (ub << 16);
}
__device__ __forceinline__ float bf16_rt(float x) {
    return __bfloat162float(__float2bfloat16_rn(x));
}
__device__ __forceinline__ void mma_bf16(float* d, const uint32_t* a,
                                         uint32_t b0, uint32_t b1) {
    asm volatile(
        "mma.sync.aligned.m16n8k16.row.col.f32.bf16.bf16.f32 "
        "{%0,%1,%2,%3}, {%4,%5,%6,%7}, {%8,%9}, {%0,%1,%2,%3};"
        : "+f"(d[0]), "+f"(d[1]), "+f"(d[2]), "+f"(d[3])
        : "r"(a[0]), "r"(a[1]), "r"(a[2]), "r"(a[3]), "r"(b0), "r"(b1));
}
__device__ __forceinline__ void ldmatrix_x4(uint32_t* r, uint32_t addr) {
    asm volatile("ldmatrix.sync.aligned.m8n8.x4.shared.b16 {%0,%1,%2,%3}, [%4];"
                 : "=r"(r[0]), "=r"(r[1]), "=r"(r[2]), "=r"(r[3]) : "r"(addr));
}

// ---------------- GEMM inner machinery (BM=128) -----------------------------------
#define AW 136   // bf16 per padded smem row

// One K=128 pass. Per katom: batch-load all 8 W fragments up front (one long
// stall window instead of two), then issue all 48 mmas j-major.
__device__ __forceinline__ void mma_pass(
    uint32_t aHiBase, uint32_t aLoBase, const uint4* __restrict__ Wtab,
    int J0, int lid, int R, float acc[2][8][4]) {
    const int lrow = (lid & 7) + ((lid >> 3) & 1) * 8;
    const int lcol = (lid >> 4) * 8;
    const uint4* wbase = Wtab + (size_t)J0 * 8 * 32 + lid;
#pragma unroll
    for (int katom = 0; katom < 8; katom++) {
        const int k0 = katom * 16;
        uint4 wf[8];
#pragma unroll
        for (int jj = 0; jj < 8; jj++)
            wf[jj] = __ldg(wbase + ((size_t)jj * 8 + katom) * 32);
        uint32_t ahi[2][4], alo[2][4];
#pragma unroll
        for (int m = 0; m < 2; m++) {
            uint32_t off = (uint32_t)((R + m * 16 + lrow) * AW + k0 + lcol) * 2;
            ldmatrix_x4(ahi[m], aHiBase + off);
            ldmatrix_x4(alo[m], aLoBase + off);
        }
#pragma unroll
        for (int jj = 0; jj < 8; jj++)
            mma_bf16(acc[0][jj], ahi[0], wf[jj].x, wf[jj].y);
#pragma unroll
        for (int jj = 0; jj < 8; jj++)
            mma_bf16(acc[1][jj], ahi[1], wf[jj].x, wf[jj].y);
#pragma unroll
        for (int jj = 0; jj < 8; jj++)
            mma_bf16(acc[0][jj], ahi[0], wf[jj].z, wf[jj].w);
#pragma unroll
        for (int jj = 0; jj < 8; jj++)
            mma_bf16(acc[1][jj], ahi[1], wf[jj].z, wf[jj].w);
#pragma unroll
        for (int jj = 0; jj < 8; jj++)
            mma_bf16(acc[0][jj], alo[0], wf[jj].x, wf[jj].y);
#pragma unroll
        for (int jj = 0; jj < 8; jj++)
            mma_bf16(acc[1][jj], alo[1], wf[jj].x, wf[jj].y);
    }
}

// Stage 128x128 fp32 rows as bf16 hi/lo in smem.
__device__ __forceinline__ void stage_tile(
    const float* __restrict__ A,
    __nv_bfloat16* sAhi, __nv_bfloat16* sAlo, int m0, int M, int tid) {
#pragma unroll
    for (int i = 0; i < 16; i++) {
        int idx = tid + i * 256;
        int row = idx >> 5;
        int c4  = idx & 31;
        int m = m0 + row;
        float4 v = make_float4(0.f, 0.f, 0.f, 0.f);
        if (m < M) v = *(const float4*)(A + (size_t)m * H + c4 * 4);
        float hx = bf16_rt(v.x), hy = bf16_rt(v.y);
        float hz = bf16_rt(v.z), hw = bf16_rt(v.w);
        uint2 hpack, lpack;
        hpack.x = pack_bf16x2(hx, hy);
        hpack.y = pack_bf16x2(hz, hw);
        lpack.x = pack_bf16x2(v.x - hx, v.y - hy);
        lpack.y = pack_bf16x2(v.z - hz, v.w - hw);
        *(uint2*)&sAhi[row * AW + c4 * 4] = hpack;
        *(uint2*)&sAlo[row * AW + c4 * 4] = lpack;
    }
}

// ---------------- small kernels -------------------------------------------------
__global__ void zero_all_kernel(float* out, int g, int n) {
    int i = blockIdx.x * blockDim.x + threadIdx.x;
    if (i < g) out[i] = 0.0f;
    if (i < n) { g_cnt[i] = 0; g_tmp[i] = 0; }
}
__global__ void hist_kernel(const int* __restrict__ ei, int Ee) {
    int e = blockIdx.x * blockDim.x + threadIdx.x;
    if (e >= Ee) return;
    atomicAdd(&g_cnt[__ldg(ei + Ee + e)], 1);
}
__global__ void scan_block_kernel(int n) {
    __shared__ int sh[1024];
    int gid = blockIdx.x * 1024 + threadIdx.x;
    int v = (gid < n) ? g_cnt[gid] : 0;
    sh[threadIdx.x] = v;
    __syncthreads();
    for (int off = 1; off < 1024; off <<= 1) {
        int t = (threadIdx.x >= off) ? sh[threadIdx.x - off] : 0;
        __syncthreads();
        sh[threadIdx.x] += t;
        __syncthreads();
    }
    if (gid < n) g_cnt[gid] = sh[threadIdx.x];
    if (threadIdx.x == 1023) g_bsum[blockIdx.x] = sh[1023];
}
__global__ void scan_bsum_kernel(int nb) {
    if (threadIdx.x == 0) {
        int acc = 0;
        for (int i = 0; i < nb; i++) { int t = g_bsum[i]; g_bsum[i] = acc; acc += t; }
    }
}
__global__ void scan_final_kernel(int n) {
    int gid = blockIdx.x * 1024 + threadIdx.x;
    if (gid < n) g_rowptr[gid + 1] = g_cnt[gid] + g_bsum[blockIdx.x];
    if (gid == 0) g_rowptr[0] = 0;
}
__global__ void fill_csr_kernel(const int* __restrict__ ei,
                                const int* __restrict__ x, int Ee) {
    int e = blockIdx.x * blockDim.x + threadIdx.x;
    if (e >= Ee) return;
    int src = __ldg(ei + e);
    int dst = __ldg(ei + Ee + e);
    int pos = g_rowptr[dst] + atomicAdd(&g_tmp[dst], 1);
    g_csr_src[pos] = src;
    g_csr_x[pos] = __ldg(x + src);
}

// layer-0 gather: agg[n] = (1+eps)*T0[x[n]] + sum_{CSR[n]} T0[x[src]]
__global__ void gather0_kernel(const int* __restrict__ x,
                               const float* __restrict__ eps,
                               float* __restrict__ agg, int Nn) {
    int n = (blockIdx.x * blockDim.x + threadIdx.x) >> 5;
    int lane = threadIdx.x & 31;
    if (n >= Nn) return;
    float sc = 1.0f + __ldg(eps);
    const float* T0 = g_T0;
    float4 self = *(const float4*)(T0 + (size_t)__ldg(x + n) * H + lane * 4);
    float4 acc;
    acc.x = self.x * sc; acc.y = self.y * sc;
    acc.z = self.z * sc; acc.w = self.w * sc;
    int s = g_rowptr[n], e = g_rowptr[n + 1];
    int i = s;
    for (; i + 3 < e; i += 4) {
        int s0 = __ldg(g_csr_x + i);
        int s1 = __ldg(g_csr_x + i + 1);
        int s2 = __ldg(g_csr_x + i + 2);
        int s3 = __ldg(g_csr_x + i + 3);
        float4 v0 = *(const float4*)(T0 + (size_t)s0 * H + lane * 4);
        float4 v1 = *(const float4*)(T0 + (size_t)s1 * H + lane * 4);
        float4 v2 = *(const float4*)(T0 + (size_t)s2 * H + lane * 4);
        float4 v3 = *(const float4*)(T0 + (size_t)s3 * H + lane * 4);
        acc.x += (v0.x + v1.x) + (v2.x + v3.x);
        acc.y += (v0.y + v1.y) + (v2.y + v3.y);
        acc.z += (v0.z + v1.z) + (v2.z + v3.z);
        acc.w += (v0.w + v1.w) + (v2.w + v3.w);
    }
    for (; i < e; i++) {
        int s0 = __ldg(g_csr_x + i);
        float4 v0 = *(const float4*)(T0 + (size_t)s0 * H + lane * 4);
        acc.x += v0.x; acc.y += v0.y; acc.z += v0.z; acc.w += v0.w;
    }
    *(float4*)(agg + (size_t)n * H + lane * 4) = acc;
}

// layers 1,2 gather: agg[n] = (1+eps)*feat[n] + sum_{CSR[n]} feat[src]
__global__ void gather_kernel(const float* __restrict__ feat,
                              const float* __restrict__ eps, int layer,
                              float* __restrict__ agg, int Nn) {
    int n = (blockIdx.x * blockDim.x + threadIdx.x) >> 5;
    int lane = threadIdx.x & 31;
    if (n >= Nn) return;
    float sc = 1.0f + __ldg(eps + layer);
    float4 self = *(const float4*)(feat + (size_t)n * H + lane * 4);
    float4 acc;
    acc.x = self.x * sc; acc.y = self.y * sc;
    acc.z = self.z * sc; acc.w = self.w * sc;
    int s = g_rowptr[n], e = g_rowptr[n + 1];
    int i = s;
    for (; i + 3 < e; i += 4) {
        int s0 = __ldg(g_csr_src + i);
        int s1 = __ldg(g_csr_src + i + 1);
        int s2 = __ldg(g_csr_src + i + 2);
        int s3 = __ldg(g_csr_src + i + 3);
        float4 v0 = *(const float4*)(feat + (size_t)s0 * H + lane * 4);
        float4 v1 = *(const float4*)(feat + (size_t)s1 * H + lane * 4);
        float4 v2 = *(const float4*)(feat + (size_t)s2 * H + lane * 4);
        float4 v3 = *(const float4*)(feat + (size_t)s3 * H + lane * 4);
        acc.x += (v0.x + v1.x) + (v2.x + v3.x);
        acc.y += (v0.y + v1.y) + (v2.y + v3.y);
        acc.z += (v0.z + v1.z) + (v2.z + v3.z);
        acc.w += (v0.w + v1.w) + (v2.w + v3.w);
    }
    for (; i < e; i++) {
        int s0 = __ldg(g_csr_src + i);
        float4 v0 = *(const float4*)(feat + (size_t)s0 * H + lane * 4);
        acc.x += v0.x; acc.y += v0.y; acc.z += v0.z; acc.w += v0.w;
    }
    *(float4*)(agg + (size_t)n * H + lane * 4) = acc;
}

// ---------------- fold stage 1 ----------------------------------------------------
__global__ void fold_scale_kernel(
    const float* __restrict__ bn_g, const float* __restrict__ bn_b,
    const float* __restrict__ bn_m, const float* __restrict__ bn_v,
    const float* __restrict__ lin_w, const float* __restrict__ lin_b,
    const float* __restrict__ mbn_g, const float* __restrict__ mbn_b,
    const float* __restrict__ mbn_m, const float* __restrict__ mbn_v,
    const float* __restrict__ mlp_w1, const float* __restrict__ mlp_b1) {
    const int b = blockIdx.x;       // 0..5
    const int n = threadIdx.x;
    if (b < 3) {
        int l = b;
        __shared__ float ss[H], st[H];
        float s = bn_g[l * H + n] * rsqrtf(bn_v[l * H + n] + BN_EPS);
        ss[n] = s;
        st[n] = bn_b[l * H + n] - bn_m[l * H + n] * s;
        __syncthreads();
        const float* W = lin_w + (size_t)l * H * H;
        float* dst = (l == 0) ? g_scr : (g_SL + (size_t)(l - 1) * H * H);
        float bias = lin_b[l * H + n];
#pragma unroll 4
        for (int c = 0; c < H; c++) {
            float w = __ldg(W + c * H + n);
            dst[c * H + n] = ss[c] * w;
            bias += st[c] * w;
        }
        if (l == 0) g_bf[n] = bias;
        else        g_bfold[(l - 1) * H + n] = bias;
    } else {
        int l = b - 3;
        float sv = mbn_g[l * H + n] * rsqrtf(mbn_v[l * H + n] + BN_EPS);
        float tv = mbn_b[l * H + n] - mbn_m[l * H + n] * sv;
        const float* W = mlp_w1 + (size_t)l * H * H;
        float* dst = g_scr + (size_t)(1 + 2 * l) * H * H;
#pragma unroll 4
        for (int k = 0; k < H; k++)
            dst[k * H + n] = __ldg(W + k * H + n) * sv;
        g_bf[(1 + 2 * l) * H + n] = mlp_b1[l * H + n] * sv + tv;
    }
}

// ---------------- fold: T0 = relu(embed_table @ SL0 + bfold0)  (100 x 128) --------
__global__ void fold_embed_kernel(const float* __restrict__ table) {
    const int v = blockIdx.x;
    const int n = threadIdx.x;
    __shared__ float row[H];
    row[n] = table[(size_t)v * H + n];
    __syncthreads();
    float acc = g_bf[n];
    const float* SL0 = g_scr;
#pragma unroll 4
    for (int c = 0; c < H; c++)
        acc += row[c] * SL0[c * H + n];
    g_T0[(size_t)v * H + n] = fmaxf(acc, 0.f);
}

// ---------------- fold stage 2: Cc_l = W2_l @ SL_{l+1}; readout fold --------------
__global__ void fold_mm_kernel(
    const float* __restrict__ mlp_w2, const float* __restrict__ mlp_b2,
    const float* __restrict__ ro_w, const float* __restrict__ ro_b) {
    const int b = blockIdx.x;       // 0..8
    if (b == 8) {
        __shared__ float ro[H];
        int t = threadIdx.x;
        if (t < H) ro[t] = ro_w[t];
        __syncthreads();
        if (t < H) {
            const float* W2 = mlp_w2 + (size_t)2 * H * H;
            float acc = 0.f;
            for (int j = 0; j < H; j++) acc += W2[t * H + j] * ro[j];
            g_rov[t] = acc;
        }
        if (t == 0) {
            const float* b2 = mlp_b2 + 2 * H;
            float acc = ro_b[0];
            for (int j = 0; j < H; j++) acc += b2[j] * ro[j];
            g_roc[0] = acc;
        }
        return;
    }
    const int l  = b >> 2;
    const int m0 = (b & 3) * 32;
    const float* W2 = mlp_w2 + (size_t)l * H * H;
    const float* SL = g_SL + (size_t)l * H * H;
    float* C = g_scr + (size_t)(2 + 2 * l) * H * H;

    __shared__ float sS[32][128];
    const int tm = threadIdx.x >> 4;
    const int tn = threadIdx.x & 15;
    float acc[2][8];
#pragma unroll
    for (int r = 0; r < 2; r++)
#pragma unroll
        for (int j = 0; j < 8; j++) acc[r][j] = 0.f;

    for (int kc = 0; kc < H; kc += 32) {
        for (int i = threadIdx.x; i < 32 * 128; i += 256)
            sS[i >> 7][i & 127] = SL[(size_t)(kc + (i >> 7)) * H + (i & 127)];
        __syncthreads();
        for (int kk = 0; kk < 32; kk++) {
            int k = kc + kk;
            float a0 = W2[(m0 + tm * 2)     * H + k];
            float a1 = W2[(m0 + tm * 2 + 1) * H + k];
#pragma unroll
            for (int j = 0; j < 8; j++) {
                float sv = sS[kk][tn * 8 + j];
                acc[0][j] += a0 * sv;
                acc[1][j] += a1 * sv;
            }
        }
        __syncthreads();
    }
#pragma unroll
    for (int r = 0; r < 2; r++)
#pragma unroll
        for (int j = 0; j < 8; j++)
            C[(size_t)(m0 + tm * 2 + r) * H + tn * 8 + j] = acc[r][j];

    if ((b & 3) == 0) {
        __syncthreads();
        int n = threadIdx.x;
        if (n < H) {
            const float* b2 = mlp_b2 + l * H;
            float a = g_bfold[l * H + n];
            for (int k = 0; k < H; k++) a += b2[k] * SL[(size_t)k * H + n];
            g_bf[(2 + 2 * l) * H + n] = a;
        }
    }
}

// ---------------- fold stage 3: pack fragments (one block per slot x katom) -------
__global__ void pack_kernel() {
    const int slot  = (blockIdx.x >> 3) + 1;   // 1..5
    const int katom = blockIdx.x & 7;          // 0..7
    const int n = threadIdx.x;
    const float* W = g_scr + (size_t)slot * H * H;
    const int J = n >> 3;
    const int g = n & 7;
#pragma unroll
    for (int tg = 0; tg < 4; tg++) {
        int k0 = katom * 16 + tg * 2;
        float v00 = W[(k0)     * H + n];
        float v01 = W[(k0 + 1) * H + n];
        float v10 = W[(k0 + 8) * H + n];
        float v11 = W[(k0 + 9) * H + n];
        float h00 = bf16_rt(v00), h01 = bf16_rt(v01);
        float h10 = bf16_rt(v10), h11 = bf16_rt(v11);
        uint4 out;
        out.x = pack_bf16x2(h00, h01);
        out.y = pack_bf16x2(h10, h11);
        out.z = pack_bf16x2(v00 - h00, v01 - h01);
        out.w = pack_bf16x2(v10 - h10, v11 - h11);
        int lane = g * 4 + tg;
        g_Wfrag[(((size_t)slot * 16 + J) * 8 + katom) * 32 + lane] = out;
    }
}

// ---------------- smem layout (BM=128) ---------------------------------------------
static constexpr int SM_AHI   = 0;
static constexpr int SM_ALO   = 128 * AW * 2;
static constexpr int SM_BIAS1 = 2 * 128 * AW * 2;
static constexpr int SM_BIAS2 = SM_BIAS1 + 512;
static constexpr int SM_RO    = SM_BIAS2 + 512;
static constexpr int SM_TOTAL_G = SM_RO + 512;

// ---------------- dual: t' = relu( relu(agg@Bz+bz) @ Cc + bc ) --------------------
__global__ void __launch_bounds__(256, 2)
gemm_dual(const float* __restrict__ A,
          const uint4* __restrict__ Wf1, const float* __restrict__ b1,
          const uint4* __restrict__ Wf2, const float* __restrict__ b2,
          float* __restrict__ Cout, int M) {
    extern __shared__ char smem[];
    __nv_bfloat16* sAhi = (__nv_bfloat16*)(smem + SM_AHI);
    __nv_bfloat16* sAlo = (__nv_bfloat16*)(smem + SM_ALO);
    float* sBias1 = (float*)(smem + SM_BIAS1);
    float* sBias2 = (float*)(smem + SM_BIAS2);

    const int tid = threadIdx.x;
    const int wid = tid >> 5, lid = tid & 31;
    const int m0 = blockIdx.x * 128;
    const int J0 = (wid >> 2) * 8;
    const int R = (wid & 3) * 32;
    const uint32_t aHiBase = smem_addr_u32(sAhi);
    const uint32_t aLoBase = smem_addr_u32(sAlo);

    if (tid < H) {
        sBias1[tid] = b1[tid];
        sBias2[tid] = b2[tid];
    }
    stage_tile(A, sAhi, sAlo, m0, M, tid);
    __syncthreads();

    float acc[2][8][4];
#pragma unroll
    for (int m = 0; m < 2; m++)
#pragma unroll
        for (int j = 0; j < 8; j++)
#pragma unroll
            for (int r = 0; r < 4; r++) acc[m][j][r] = 0.0f;

    mma_pass(aHiBase, aLoBase, Wf1, J0, lid, R, acc);

    const int cb = (wid >> 2) * 64;
    const int g = lid >> 2, tg = lid & 3;

    __syncthreads();
#pragma unroll
    for (int m = 0; m < 2; m++)
#pragma unroll
        for (int rh = 0; rh < 2; rh++) {
            int row = R + m * 16 + rh * 8 + g;
#pragma unroll
            for (int j = 0; j < 8; j++) {
                int c = cb + j * 8 + tg * 2;
                float zx = fmaxf(acc[m][j][rh * 2 + 0] + sBias1[c], 0.f);
                float zy = fmaxf(acc[m][j][rh * 2 + 1] + sBias1[c + 1], 0.f);
                float hx = bf16_rt(zx), hy = bf16_rt(zy);
                *(uint32_t*)&sAhi[row * AW + c] = pack_bf16x2(hx, hy);
                *(uint32_t*)&sAlo[row * AW + c] = pack_bf16x2(zx - hx, zy - hy);
            }
        }
    __syncthreads();

#pragma unroll
    for (int m = 0; m < 2; m++)
#pragma unroll
        for (int j = 0; j < 8; j++)
#pragma unroll
            for (int r = 0; r < 4; r++) acc[m][j][r] = 0.0f;

    mma_pass(aHiBase, aLoBase, Wf2, J0, lid, R, acc);

    const int r0 = m0 + R;
#pragma unroll
    for (int m = 0; m < 2; m++)
#pragma unroll
        for (int rh = 0; rh < 2; rh++) {
            int row = r0 + m * 16 + rh * 8 + g;
            if (row < M) {
#pragma unroll
                for (int j = 0; j < 8; j++) {
                    int c = cb + j * 8 + tg * 2;
                    float2 o;
                    o.x = fmaxf(acc[m][j][rh * 2 + 0] + sBias2[c], 0.f);
                    o.y = fmaxf(acc[m][j][rh * 2 + 1] + sBias2[c + 1], 0.f);
                    *(float2*)(Cout + (size_t)row * H + c) = o;
                }
            }
        }
}

// ---------------- layer-2: z = relu(agg@Bz2+bz2); out += z.v + c -----------------
__global__ void __launch_bounds__(256, 2)
gemm_ro(const float* __restrict__ A,
        const uint4* __restrict__ Wf, const float* __restrict__ bias,
        const int* __restrict__ batch, float* __restrict__ gout, int M) {
    extern __shared__ char smem[];
    __nv_bfloat16* sAhi = (__nv_bfloat16*)(smem + SM_AHI);
    __nv_bfloat16* sAlo = (__nv_bfloat16*)(smem + SM_ALO);
    float* sBias = (float*)(smem + SM_BIAS1);
    float* sRo   = (float*)(smem + SM_RO);

    const int tid = threadIdx.x;
    const int wid = tid >> 5, lid = tid & 31;
    const int m0 = blockIdx.x * 128;
    const int J0 = (wid >> 2) * 8;
    const int R = (wid & 3) * 32;

    if (tid < H) {
        sBias[tid] = bias[tid];
        sRo[tid] = g_rov[tid];
    }
    stage_tile(A, sAhi, sAlo, m0, M, tid);
    __syncthreads();

    float acc[2][8][4];
#pragma unroll
    for (int m = 0; m < 2; m++)
#pragma unroll
        for (int j = 0; j < 8; j++)
#pragma unroll
            for (int r = 0; r < 4; r++) acc[m][j][r] = 0.0f;

    mma_pass(smem_addr_u32(sAhi), smem_addr_u32(sAlo), Wf, J0, lid, R, acc);

    const int r0 = m0 + R;
    const int cb = (wid >> 2) * 64;
    const int g = lid >> 2, tg = lid & 3;
    const float roc = g_roc[0];
    float dots[4] = {0.f, 0.f, 0.f, 0.f};
#pragma unroll
    for (int m = 0; m < 2; m++)
#pragma unroll
        for (int rh = 0; rh < 2; rh++) {
            int row = r0 + m * 16 + rh * 8 + g;
            if (row < M) {
                float dv = 0.f;
#pragma unroll
                for (int j = 0; j < 8; j++) {
                    int c = cb + j * 8 + tg * 2;
                    float zx = fmaxf(acc[m][j][rh * 2 + 0] + sBias[c], 0.f);
                    float zy = fmaxf(acc[m][j][rh * 2 + 1] + sBias[c + 1], 0.f);
                    dv += zx * sRo[c] + zy * sRo[c + 1];
                }
                dots[m * 2 + rh] = dv;
            }
        }
#pragma unroll
    for (int s = 0; s < 4; s++) {
        float v = dots[s];
        v += __shfl_xor_sync(0xffffffff, v, 1);
        v += __shfl_xor_sync(0xffffffff, v, 2);
        int row = r0 + (s >> 1) * 16 + (s & 1) * 8 + g;
        if (tg == 0 && row < M) {
            if (cb == 0) v += roc;
            atomicAdd(gout + __ldg(batch + row), v);
        }
    }
}

// ---------------- launcher ------------------------------------------------------
extern "C" void kernel_launch(void* const* d_in, const int* in_sizes, int n_in,
                              void* d_out, int out_size) {
    const int*   x      = (const int*)d_in[0];
    const int*   ei     = (const int*)d_in[1];
    const int*   batch  = (const int*)d_in[2];
    const float* table  = (const float*)d_in[3];
    const float* bn_g   = (const float*)d_in[4];
    const float* bn_b   = (const float*)d_in[5];
    const float* bn_m   = (const float*)d_in[6];
    const float* bn_v   = (const float*)d_in[7];
    const float* lin_w  = (const float*)d_in[8];
    const float* lin_b  = (const float*)d_in[9];
    const float* eps    = (const float*)d_in[10];
    const float* mlp_w1 = (const float*)d_in[11];
    const float* mlp_b1 = (const float*)d_in[12];
    const float* mbn_g  = (const float*)d_in[13];
    const float* mbn_b  = (const float*)d_in[14];
    const float* mbn_m  = (const float*)d_in[15];
    const float* mbn_v  = (const float*)d_in[16];
    const float* mlp_w2 = (const float*)d_in[17];
    const float* mlp_b2 = (const float*)d_in[18];
    const float* ro_w   = (const float*)d_in[19];
    const float* ro_b   = (const float*)d_in[20];

    const int Nn = in_sizes[0];
    const int Ee = in_sizes[1] / 2;
    const int Gg = out_size;

    float *t, *agg, *bf;
    uint4* Wf;
    cudaGetSymbolAddress((void**)&t,   g_t);
    cudaGetSymbolAddress((void**)&agg, g_agg);
    cudaGetSymbolAddress((void**)&Wf,  g_Wfrag);
    cudaGetSymbolAddress((void**)&bf,  g_bf);

    cudaFuncSetAttribute(gemm_dual, cudaFuncAttributeMaxDynamicSharedMemorySize, SM_TOTAL_G);
    cudaFuncSetAttribute(gemm_ro,   cudaFuncAttributeMaxDynamicSharedMemorySize, SM_TOTAL_G);

    const int gemm_grid = (Nn + 127) / 128;
    const int edge_grid = (Ee + 255) / 256;
    const int node_grid = (Nn + 1023) / 1024;
    const int warp_grid = ((Nn * 32) + 255) / 256;

    const size_t SLOT = (size_t)16 * 8 * 32;

    // fold pipeline (embed GEMM folded into a 100x128 table T0)
    fold_scale_kernel<<<6, H>>>(bn_g, bn_b, bn_m, bn_v, lin_w, lin_b,
                                mbn_g, mbn_b, mbn_m, mbn_v, mlp_w1, mlp_b1);
    fold_embed_kernel<<<100, H>>>(table);
    fold_mm_kernel<<<9, 256>>>(mlp_w2, mlp_b2, ro_w, ro_b);
    pack_kernel<<<40, H>>>();
    // output zero + CSR build
    zero_all_kernel<<<(Nn + 255) / 256, 256>>>((float*)d_out, Gg, Nn);
    hist_kernel<<<edge_grid, 256>>>(ei, Ee);
    scan_block_kernel<<<node_grid, 1024>>>(Nn);
    scan_bsum_kernel<<<1, 32>>>(node_grid);
    scan_final_kernel<<<node_grid, 1024>>>(Nn);
    fill_csr_kernel<<<edge_grid, 256>>>(ei, x, Ee);

    // layer 0: L1-resident gather from T0 + dual
    gather0_kernel<<<warp_grid, 256>>>(x, eps, agg, Nn);
    gemm_dual<<<gemm_grid, 256, SM_TOTAL_G>>>(
        agg, Wf + 1 * SLOT, bf + 1 * H, Wf + 2 * SLOT, bf + 2 * H, t, Nn);
    // layer 1
    gather_kernel<<<warp_grid, 256>>>(t, eps, 1, agg, Nn);
    gemm_dual<<<gemm_grid, 256, SM_TOTAL_G>>>(
        agg, Wf + 3 * SLOT, bf + 3 * H, Wf + 4 * SLOT, bf + 4 * H, t, Nn);
    // layer 2: gather + z-GEMM + folded readout
    gather_kernel<<<warp_grid, 256>>>(t, eps, 2, agg, Nn);
    gemm_ro<<<gemm_grid, 256, SM_TOTAL_G>>>(
        agg, Wf + 5 * SLOT, bf + 5 * H, batch, (float*)d_out, Nn);
}

// round 16
// speedup vs baseline: 1.0284x; 1.0284x over previous
#include <cuda_runtime.h>
#include <cuda_bf16.h>
#include <cstdint>

#define H 128
#define MAXN 50000
#define MAXE 800000
#define BN_EPS 1e-5f

// ---------------- device scratch ---------------------------------------------
__device__ float g_t[MAXN * H];
__device__ float g_agg[MAXN * H];
// Fragment slots: 1:Bz0 2:Cc0 3:Bz1 4:Cc1 5:Bz2
__device__ uint4 g_Wfrag[6 * 16 * 8 * 32];
__device__ float g_bf[6 * H];
// fp32 fold scratch
__device__ float g_scr[6 * H * H];
__device__ float g_SL[2 * H * H];
__device__ float g_bfold[2 * H];
__device__ float g_rov[H];
__device__ float g_roc[1];
__device__ float g_T0[100 * H];       // relu(embed_table @ SL0 + bfold0)
// CSR scratch
__device__ int g_cnt[MAXN];
__device__ int g_tmp[MAXN];
__device__ int g_rowptr[MAXN + 1];
__device__ int g_csr_src[MAXE];
__device__ int g_csr_x[MAXE];
__device__ int g_bsum[64];

// ---------------- helpers -------------------------------------------------------
__device__ __forceinline__ uint32_t smem_addr_u32(const void* p) {
    uint32_t a;
    asm("{ .reg .u64 t; cvta.to.shared.u64 t, %1; cvt.u32.u64 %0, t; }" : "=r"(a) : "l"(p));
    return a;
}
__device__ __forceinline__ uint32_t pack_bf16x2(float a, float b) {
    uint32_t ua = (uint32_t)__bfloat16_as_ushort(__float2bfloat16_rn(a));
    uint32_t ub = (uint32_t)__bfloat16_as_ushort(__float2bfloat16_rn(b));
    return ua | (ub << 16);
}
__device__ __forceinline__ float bf16_rt(float x) {
    return __bfloat162float(__float2bfloat16_rn(x));
}
__device__ __forceinline__ void mma_bf16(float* d, const uint32_t* a,
                                         uint32_t b0, uint32_t b1) {
    asm volatile(
        "mma.sync.aligned.m16n8k16.row.col.f32.bf16.bf16.f32 "
        "{%0,%1,%2,%3}, {%4,%5,%6,%7}, {%8,%9}, {%0,%1,%2,%3};"
        : "+f"(d[0]), "+f"(d[1]), "+f"(d[2]), "+f"(d[3])
        : "r"(a[0]), "r"(a[1]), "r"(a[2]), "r"(a[3]), "r"(b0), "r"(b1));
}
__device__ __forceinline__ void ldmatrix_x4(uint32_t* r, uint32_t addr) {
    asm volatile("ldmatrix.sync.aligned.m8n8.x4.shared.b16 {%0,%1,%2,%3}, [%4];"
                 : "=r"(r[0]), "=r"(r[1]), "=r"(r[2]), "=r"(r[3]) : "r"(addr));
}

// ---------------- GEMM inner machinery (BM=128, grouped W loads: r13/14 config) --
#define AW 136   // bf16 per padded smem row

__device__ __forceinline__ void mma_pass(
    uint32_t aHiBase, uint32_t aLoBase, const uint4* __restrict__ Wtab,
    int J0, int lid, int R, float acc[2][8][4]) {
    const int lrow = (lid & 7) + ((lid >> 3) & 1) * 8;
    const int lcol = (lid >> 4) * 8;
#pragma unroll
    for (int katom = 0; katom < 8; katom++) {
        const int k0 = katom * 16;
        uint32_t ahi[2][4], alo[2][4];
#pragma unroll
        for (int m = 0; m < 2; m++) {
            uint32_t off = (uint32_t)((R + m * 16 + lrow) * AW + k0 + lcol) * 2;
            ldmatrix_x4(ahi[m], aHiBase + off);
            ldmatrix_x4(alo[m], aLoBase + off);
        }
#pragma unroll
        for (int grp = 0; grp < 2; grp++) {
            uint4 wf[4];
#pragma unroll
            for (int jj = 0; jj < 4; jj++)
                wf[jj] = __ldg(&Wtab[(((size_t)(J0 + grp * 4 + jj)) * 8 + katom) * 32 + lid]);
#pragma unroll
            for (int jj = 0; jj < 4; jj++)
                mma_bf16(acc[0][grp * 4 + jj], ahi[0], wf[jj].x, wf[jj].y);
#pragma unroll
            for (int jj = 0; jj < 4; jj++)
                mma_bf16(acc[1][grp * 4 + jj], ahi[1], wf[jj].x, wf[jj].y);
#pragma unroll
            for (int jj = 0; jj < 4; jj++)
                mma_bf16(acc[0][grp * 4 + jj], ahi[0], wf[jj].z, wf[jj].w);
#pragma unroll
            for (int jj = 0; jj < 4; jj++)
                mma_bf16(acc[1][grp * 4 + jj], ahi[1], wf[jj].z, wf[jj].w);
#pragma unroll
            for (int jj = 0; jj < 4; jj++)
                mma_bf16(acc[0][grp * 4 + jj], alo[0], wf[jj].x, wf[jj].y);
#pragma unroll
            for (int jj = 0; jj < 4; jj++)
                mma_bf16(acc[1][grp * 4 + jj], alo[1], wf[jj].x, wf[jj].y);
        }
    }
}

// Stage 128x128 fp32 rows as bf16 hi/lo in smem.
__device__ __forceinline__ void stage_tile(
    const float* __restrict__ A,
    __nv_bfloat16* sAhi, __nv_bfloat16* sAlo, int m0, int M, int tid) {
#pragma unroll
    for (int i = 0; i < 16; i++) {
        int idx = tid + i * 256;
        int row = idx >> 5;
        int c4  = idx & 31;
        int m = m0 + row;
        float4 v = make_float4(0.f, 0.f, 0.f, 0.f);
        if (m < M) v = *(const float4*)(A + (size_t)m * H + c4 * 4);
        float hx = bf16_rt(v.x), hy = bf16_rt(v.y);
        float hz = bf16_rt(v.z), hw = bf16_rt(v.w);
        uint2 hpack, lpack;
        hpack.x = pack_bf16x2(hx, hy);
        hpack.y = pack_bf16x2(hz, hw);
        lpack.x = pack_bf16x2(v.x - hx, v.y - hy);
        lpack.y = pack_bf16x2(v.z - hz, v.w - hw);
        *(uint2*)&sAhi[row * AW + c4 * 4] = hpack;
        *(uint2*)&sAlo[row * AW + c4 * 4] = lpack;
    }
}

// ---------------- small kernels -------------------------------------------------
__global__ void zero_all_kernel(float* out, int g, int n) {
    int i = blockIdx.x * blockDim.x + threadIdx.x;
    if (i < g) out[i] = 0.0f;
    if (i < n) { g_cnt[i] = 0; g_tmp[i] = 0; }
}
__global__ void hist_kernel(const int* __restrict__ ei, int Ee) {
    int e = blockIdx.x * blockDim.x + threadIdx.x;
    if (e >= Ee) return;
    atomicAdd(&g_cnt[__ldg(ei + Ee + e)], 1);
}
__global__ void scan_block_kernel(int n) {
    __shared__ int sh[1024];
    int gid = blockIdx.x * 1024 + threadIdx.x;
    int v = (gid < n) ? g_cnt[gid] : 0;
    sh[threadIdx.x] = v;
    __syncthreads();
    for (int off = 1; off < 1024; off <<= 1) {
        int t = (threadIdx.x >= off) ? sh[threadIdx.x - off] : 0;
        __syncthreads();
        sh[threadIdx.x] += t;
        __syncthreads();
    }
    if (gid < n) g_cnt[gid] = sh[threadIdx.x];
    if (threadIdx.x == 1023) g_bsum[blockIdx.x] = sh[1023];
}
__global__ void scan_bsum_kernel(int nb) {
    if (threadIdx.x == 0) {
        int acc = 0;
        for (int i = 0; i < nb; i++) { int t = g_bsum[i]; g_bsum[i] = acc; acc += t; }
    }
}
__global__ void scan_final_kernel(int n) {
    int gid = blockIdx.x * 1024 + threadIdx.x;
    if (gid < n) g_rowptr[gid + 1] = g_cnt[gid] + g_bsum[blockIdx.x];
    if (gid == 0) g_rowptr[0] = 0;
}
__global__ void fill_csr_kernel(const int* __restrict__ ei,
                                const int* __restrict__ x, int Ee) {
    int e = blockIdx.x * blockDim.x + threadIdx.x;
    if (e >= Ee) return;
    int src = __ldg(ei + e);
    int dst = __ldg(ei + Ee + e);
    int pos = g_rowptr[dst] + atomicAdd(&g_tmp[dst], 1);
    g_csr_src[pos] = src;
    g_csr_x[pos] = __ldg(x + src);
}

// layer-0 gather: agg[n] = (1+eps)*T0[x[n]] + sum_{CSR[n]} T0[x[src]]
__global__ void gather0_kernel(const int* __restrict__ x,
                               const float* __restrict__ eps,
                               float* __restrict__ agg, int Nn) {
    int n = (blockIdx.x * blockDim.x + threadIdx.x) >> 5;
    int lane = threadIdx.x & 31;
    if (n >= Nn) return;
    float sc = 1.0f + __ldg(eps);
    const float* T0 = g_T0;
    float4 self = *(const float4*)(T0 + (size_t)__ldg(x + n) * H + lane * 4);
    float4 acc;
    acc.x = self.x * sc; acc.y = self.y * sc;
    acc.z = self.z * sc; acc.w = self.w * sc;
    int s = g_rowptr[n], e = g_rowptr[n + 1];
    int i = s;
    for (; i + 3 < e; i += 4) {
        int s0 = __ldg(g_csr_x + i);
        int s1 = __ldg(g_csr_x + i + 1);
        int s2 = __ldg(g_csr_x + i + 2);
        int s3 = __ldg(g_csr_x + i + 3);
        float4 v0 = *(const float4*)(T0 + (size_t)s0 * H + lane * 4);
        float4 v1 = *(const float4*)(T0 + (size_t)s1 * H + lane * 4);
        float4 v2 = *(const float4*)(T0 + (size_t)s2 * H + lane * 4);
        float4 v3 = *(const float4*)(T0 + (size_t)s3 * H + lane * 4);
        acc.x += (v0.x + v1.x) + (v2.x + v3.x);
        acc.y += (v0.y + v1.y) + (v2.y + v3.y);
        acc.z += (v0.z + v1.z) + (v2.z + v3.z);
        acc.w += (v0.w + v1.w) + (v2.w + v3.w);
    }
    for (; i < e; i++) {
        int s0 = __ldg(g_csr_x + i);
        float4 v0 = *(const float4*)(T0 + (size_t)s0 * H + lane * 4);
        acc.x += v0.x; acc.y += v0.y; acc.z += v0.z; acc.w += v0.w;
    }
    *(float4*)(agg + (size_t)n * H + lane * 4) = acc;
}

// layers 1,2 gather: agg[n] = (1+eps)*feat[n] + sum_{CSR[n]} feat[src]
__global__ void gather_kernel(const float* __restrict__ feat,
                              const float* __restrict__ eps, int layer,
                              float* __restrict__ agg, int Nn) {
    int n = (blockIdx.x * blockDim.x + threadIdx.x) >> 5;
    int lane = threadIdx.x & 31;
    if (n >= Nn) return;
    float sc = 1.0f + __ldg(eps + layer);
    float4 self = *(const float4*)(feat + (size_t)n * H + lane * 4);
    float4 acc;
    acc.x = self.x * sc; acc.y = self.y * sc;
    acc.z = self.z * sc; acc.w = self.w * sc;
    int s = g_rowptr[n], e = g_rowptr[n + 1];
    int i = s;
    for (; i + 3 < e; i += 4) {
        int s0 = __ldg(g_csr_src + i);
        int s1 = __ldg(g_csr_src + i + 1);
        int s2 = __ldg(g_csr_src + i + 2);
        int s3 = __ldg(g_csr_src + i + 3);
        float4 v0 = *(const float4*)(feat + (size_t)s0 * H + lane * 4);
        float4 v1 = *(const float4*)(feat + (size_t)s1 * H + lane * 4);
        float4 v2 = *(const float4*)(feat + (size_t)s2 * H + lane * 4);
        float4 v3 = *(const float4*)(feat + (size_t)s3 * H + lane * 4);
        acc.x += (v0.x + v1.x) + (v2.x + v3.x);
        acc.y += (v0.y + v1.y) + (v2.y + v3.y);
        acc.z += (v0.z + v1.z) + (v2.z + v3.z);
        acc.w += (v0.w + v1.w) + (v2.w + v3.w);
    }
    for (; i < e; i++) {
        int s0 = __ldg(g_csr_src + i);
        float4 v0 = *(const float4*)(feat + (size_t)s0 * H + lane * 4);
        acc.x += v0.x; acc.y += v0.y; acc.z += v0.z; acc.w += v0.w;
    }
    *(float4*)(agg + (size_t)n * H + lane * 4) = acc;
}

// ---------------- fold stage 1 ----------------------------------------------------
__global__ void fold_scale_kernel(
    const float* __restrict__ bn_g, const float* __restrict__ bn_b,
    const float* __restrict__ bn_m, const float* __restrict__ bn_v,
    const float* __restrict__ lin_w, const float* __restrict__ lin_b,
    const float* __restrict__ mbn_g, const float* __restrict__ mbn_b,
    const float* __restrict__ mbn_m, const float* __restrict__ mbn_v,
    const float* __restrict__ mlp_w1, const float* __restrict__ mlp_b1) {
    const int b = blockIdx.x;       // 0..5
    const int n = threadIdx.x;
    if (b < 3) {
        int l = b;
        __shared__ float ss[H], st[H];
        float s = bn_g[l * H + n] * rsqrtf(bn_v[l * H + n] + BN_EPS);
        ss[n] = s;
        st[n] = bn_b[l * H + n] - bn_m[l * H + n] * s;
        __syncthreads();
        const float* W = lin_w + (size_t)l * H * H;
        float* dst = (l == 0) ? g_scr : (g_SL + (size_t)(l - 1) * H * H);
        float bias = lin_b[l * H + n];
#pragma unroll 4
        for (int c = 0; c < H; c++) {
            float w = __ldg(W + c * H + n);
            dst[c * H + n] = ss[c] * w;
            bias += st[c] * w;
        }
        if (l == 0) g_bf[n] = bias;
        else        g_bfold[(l - 1) * H + n] = bias;
    } else {
        int l = b - 3;
        float sv = mbn_g[l * H + n] * rsqrtf(mbn_v[l * H + n] + BN_EPS);
        float tv = mbn_b[l * H + n] - mbn_m[l * H + n] * sv;
        const float* W = mlp_w1 + (size_t)l * H * H;
        float* dst = g_scr + (size_t)(1 + 2 * l) * H * H;
#pragma unroll 4
        for (int k = 0; k < H; k++)
            dst[k * H + n] = __ldg(W + k * H + n) * sv;
        g_bf[(1 + 2 * l) * H + n] = mlp_b1[l * H + n] * sv + tv;
    }
}

// ---------------- fold: T0 = relu(embed_table @ SL0 + bfold0)  (100 x 128) --------
__global__ void fold_embed_kernel(const float* __restrict__ table) {
    const int v = blockIdx.x;
    const int n = threadIdx.x;
    __shared__ float row[H];
    row[n] = table[(size_t)v * H + n];
    __syncthreads();
    float acc = g_bf[n];
    const float* SL0 = g_scr;
#pragma unroll 4
    for (int c = 0; c < H; c++)
        acc += row[c] * SL0[c * H + n];
    g_T0[(size_t)v * H + n] = fmaxf(acc, 0.f);
}

// ---------------- fold stage 2: Cc_l = W2_l @ SL_{l+1}; readout fold --------------
__global__ void fold_mm_kernel(
    const float* __restrict__ mlp_w2, const float* __restrict__ mlp_b2,
    const float* __restrict__ ro_w, const float* __restrict__ ro_b) {
    const int b = blockIdx.x;       // 0..8
    if (b == 8) {
        __shared__ float ro[H];
        int t = threadIdx.x;
        if (t < H) ro[t] = ro_w[t];
        __syncthreads();
        if (t < H) {
            const float* W2 = mlp_w2 + (size_t)2 * H * H;
            float acc = 0.f;
            for (int j = 0; j < H; j++) acc += W2[t * H + j] * ro[j];
            g_rov[t] = acc;
        }
        if (t == 0) {
            const float* b2 = mlp_b2 + 2 * H;
            float acc = ro_b[0];
            for (int j = 0; j < H; j++) acc += b2[j] * ro[j];
            g_roc[0] = acc;
        }
        return;
    }
    const int l  = b >> 2;
    const int m0 = (b & 3) * 32;
    const float* W2 = mlp_w2 + (size_t)l * H * H;
    const float* SL = g_SL + (size_t)l * H * H;
    float* C = g_scr + (size_t)(2 + 2 * l) * H * H;

    __shared__ float sS[32][128];
    const int tm = threadIdx.x >> 4;
    const int tn = threadIdx.x & 15;
    float acc[2][8];
#pragma unroll
    for (int r = 0; r < 2; r++)
#pragma unroll
        for (int j = 0; j < 8; j++) acc[r][j] = 0.f;

    for (int kc = 0; kc < H; kc += 32) {
        for (int i = threadIdx.x; i < 32 * 128; i += 256)
            sS[i >> 7][i & 127] = SL[(size_t)(kc + (i >> 7)) * H + (i & 127)];
        __syncthreads();
        for (int kk = 0; kk < 32; kk++) {
            int k = kc + kk;
            float a0 = W2[(m0 + tm * 2)     * H + k];
            float a1 = W2[(m0 + tm * 2 + 1) * H + k];
#pragma unroll
            for (int j = 0; j < 8; j++) {
                float sv = sS[kk][tn * 8 + j];
                acc[0][j] += a0 * sv;
                acc[1][j] += a1 * sv;
            }
        }
        __syncthreads();
    }
#pragma unroll
    for (int r = 0; r < 2; r++)
#pragma unroll
        for (int j = 0; j < 8; j++)
            C[(size_t)(m0 + tm * 2 + r) * H + tn * 8 + j] = acc[r][j];

    if ((b & 3) == 0) {
        __syncthreads();
        int n = threadIdx.x;
        if (n < H) {
            const float* b2 = mlp_b2 + l * H;
            float a = g_bfold[l * H + n];
            for (int k = 0; k < H; k++) a += b2[k] * SL[(size_t)k * H + n];
            g_bf[(2 + 2 * l) * H + n] = a;
        }
    }
}

// ---------------- fold stage 3: pack fragments (one block per slot x katom) -------
__global__ void pack_kernel() {
    const int slot  = (blockIdx.x >> 3) + 1;   // 1..5
    const int katom = blockIdx.x & 7;          // 0..7
    const int n = threadIdx.x;
    const float* W = g_scr + (size_t)slot * H * H;
    const int J = n >> 3;
    const int g = n & 7;
#pragma unroll
    for (int tg = 0; tg < 4; tg++) {
        int k0 = katom * 16 + tg * 2;
        float v00 = W[(k0)     * H + n];
        float v01 = W[(k0 + 1) * H + n];
        float v10 = W[(k0 + 8) * H + n];
        float v11 = W[(k0 + 9) * H + n];
        float h00 = bf16_rt(v00), h01 = bf16_rt(v01);
        float h10 = bf16_rt(v10), h11 = bf16_rt(v11);
        uint4 out;
        out.x = pack_bf16x2(h00, h01);
        out.y = pack_bf16x2(h10, h11);
        out.z = pack_bf16x2(v00 - h00, v01 - h01);
        out.w = pack_bf16x2(v10 - h10, v11 - h11);
        int lane = g * 4 + tg;
        g_Wfrag[(((size_t)slot * 16 + J) * 8 + katom) * 32 + lane] = out;
    }
}

// ---------------- smem layout (BM=128) ---------------------------------------------
static constexpr int SM_AHI   = 0;
static constexpr int SM_ALO   = 128 * AW * 2;
static constexpr int SM_BIAS1 = 2 * 128 * AW * 2;
static constexpr int SM_BIAS2 = SM_BIAS1 + 512;
static constexpr int SM_RO    = SM_BIAS2 + 512;
static constexpr int SM_TOTAL_G = SM_RO + 512;

// ---------------- dual: t' = relu( relu(agg@Bz+bz) @ Cc + bc ) --------------------
__global__ void __launch_bounds__(256, 2)
gemm_dual(const float* __restrict__ A,
          const uint4* __restrict__ Wf1, const float* __restrict__ b1,
          const uint4* __restrict__ Wf2, const float* __restrict__ b2,
          float* __restrict__ Cout, int M) {
    extern __shared__ char smem[];
    __nv_bfloat16* sAhi = (__nv_bfloat16*)(smem + SM_AHI);
    __nv_bfloat16* sAlo = (__nv_bfloat16*)(smem + SM_ALO);
    float* sBias1 = (float*)(smem + SM_BIAS1);
    float* sBias2 = (float*)(smem + SM_BIAS2);

    const int tid = threadIdx.x;
    const int wid = tid >> 5, lid = tid & 31;
    const int m0 = blockIdx.x * 128;
    const int J0 = (wid >> 2) * 8;
    const int R = (wid & 3) * 32;
    const uint32_t aHiBase = smem_addr_u32(sAhi);
    const uint32_t aLoBase = smem_addr_u32(sAlo);

    if (tid < H) {
        sBias1[tid] = b1[tid];
        sBias2[tid] = b2[tid];
    }
    stage_tile(A, sAhi, sAlo, m0, M, tid);
    __syncthreads();

    float acc[2][8][4];
#pragma unroll
    for (int m = 0; m < 2; m++)
#pragma unroll
        for (int j = 0; j < 8; j++)
#pragma unroll
            for (int r = 0; r < 4; r++) acc[m][j][r] = 0.0f;

    mma_pass(aHiBase, aLoBase, Wf1, J0, lid, R, acc);

    const int cb = (wid >> 2) * 64;
    const int g = lid >> 2, tg = lid & 3;

    __syncthreads();
#pragma unroll
    for (int m = 0; m < 2; m++)
#pragma unroll
        for (int rh = 0; rh < 2; rh++) {
            int row = R + m * 16 + rh * 8 + g;
#pragma unroll
            for (int j = 0; j < 8; j++) {
                int c = cb + j * 8 + tg * 2;
                float zx = fmaxf(acc[m][j][rh * 2 + 0] + sBias1[c], 0.f);
                float zy = fmaxf(acc[m][j][rh * 2 + 1] + sBias1[c + 1], 0.f);
                float hx = bf16_rt(zx), hy = bf16_rt(zy);
                *(uint32_t*)&sAhi[row * AW + c] = pack_bf16x2(hx, hy);
                *(uint32_t*)&sAlo[row * AW + c] = pack_bf16x2(zx - hx, zy - hy);
            }
        }
    __syncthreads();

#pragma unroll
    for (int m = 0; m < 2; m++)
#pragma unroll
        for (int j = 0; j < 8; j++)
#pragma unroll
            for (int r = 0; r < 4; r++) acc[m][j][r] = 0.0f;

    mma_pass(aHiBase, aLoBase, Wf2, J0, lid, R, acc);

    const int r0 = m0 + R;
#pragma unroll
    for (int m = 0; m < 2; m++)
#pragma unroll
        for (int rh = 0; rh < 2; rh++) {
            int row = r0 + m * 16 + rh * 8 + g;
            if (row < M) {
#pragma unroll
                for (int j = 0; j < 8; j++) {
                    int c = cb + j * 8 + tg * 2;
                    float2 o;
                    o.x = fmaxf(acc[m][j][rh * 2 + 0] + sBias2[c], 0.f);
                    o.y = fmaxf(acc[m][j][rh * 2 + 1] + sBias2[c + 1], 0.f);
                    *(float2*)(Cout + (size_t)row * H + c) = o;
                }
            }
        }
}

// ---------------- layer-2: z = relu(agg@Bz2+bz2); out += z.v + c -----------------
__global__ void __launch_bounds__(256, 2)
gemm_ro(const float* __restrict__ A,
        const uint4* __restrict__ Wf, const float* __restrict__ bias,
        const int* __restrict__ batch, float* __restrict__ gout, int M) {
    extern __shared__ char smem[];
    __nv_bfloat16* sAhi = (__nv_bfloat16*)(smem + SM_AHI);
    __nv_bfloat16* sAlo = (__nv_bfloat16*)(smem + SM_ALO);
    float* sBias = (float*)(smem + SM_BIAS1);
    float* sRo   = (float*)(smem + SM_RO);

    const int tid = threadIdx.x;
    const int wid = tid >> 5, lid = tid & 31;
    const int m0 = blockIdx.x * 128;
    const int J0 = (wid >> 2) * 8;
    const int R = (wid & 3) * 32;

    if (tid < H) {
        sBias[tid] = bias[tid];
        sRo[tid] = g_rov[tid];
    }
    stage_tile(A, sAhi, sAlo, m0, M, tid);
    __syncthreads();

    float acc[2][8][4];
#pragma unroll
    for (int m = 0; m < 2; m++)
#pragma unroll
        for (int j = 0; j < 8; j++)
#pragma unroll
            for (int r = 0; r < 4; r++) acc[m][j][r] = 0.0f;

    mma_pass(smem_addr_u32(sAhi), smem_addr_u32(sAlo), Wf, J0, lid, R, acc);

    const int r0 = m0 + R;
    const int cb = (wid >> 2) * 64;
    const int g = lid >> 2, tg = lid & 3;
    const float roc = g_roc[0];
    float dots[4] = {0.f, 0.f, 0.f, 0.f};
#pragma unroll
    for (int m = 0; m < 2; m++)
#pragma unroll
        for (int rh = 0; rh < 2; rh++) {
            int row = r0 + m * 16 + rh * 8 + g;
            if (row < M) {
                float dv = 0.f;
#pragma unroll
                for (int j = 0; j < 8; j++) {
                    int c = cb + j * 8 + tg * 2;
                    float zx = fmaxf(acc[m][j][rh * 2 + 0] + sBias[c], 0.f);
                    float zy = fmaxf(acc[m][j][rh * 2 + 1] + sBias[c + 1], 0.f);
                    dv += zx * sRo[c] + zy * sRo[c + 1];
                }
                dots[m * 2 + rh] = dv;
            }
        }
#pragma unroll
    for (int s = 0; s < 4; s++) {
        float v = dots[s];
        v += __shfl_xor_sync(0xffffffff, v, 1);
        v += __shfl_xor_sync(0xffffffff, v, 2);
        int row = r0 + (s >> 1) * 16 + (s & 1) * 8 + g;
        if (tg == 0 && row < M) {
            if (cb == 0) v += roc;
            atomicAdd(gout + __ldg(batch + row), v);
        }
    }
}

// ---------------- launcher ------------------------------------------------------
extern "C" void kernel_launch(void* const* d_in, const int* in_sizes, int n_in,
                              void* d_out, int out_size) {
    const int*   x      = (const int*)d_in[0];
    const int*   ei     = (const int*)d_in[1];
    const int*   batch  = (const int*)d_in[2];
    const float* table  = (const float*)d_in[3];
    const float* bn_g   = (const float*)d_in[4];
    const float* bn_b   = (const float*)d_in[5];
    const float* bn_m   = (const float*)d_in[6];
    const float* bn_v   = (const float*)d_in[7];
    const float* lin_w  = (const float*)d_in[8];
    const float* lin_b  = (const float*)d_in[9];
    const float* eps    = (const float*)d_in[10];
    const float* mlp_w1 = (const float*)d_in[11];
    const float* mlp_b1 = (const float*)d_in[12];
    const float* mbn_g  = (const float*)d_in[13];
    const float* mbn_b  = (const float*)d_in[14];
    const float* mbn_m  = (const float*)d_in[15];
    const float* mbn_v  = (const float*)d_in[16];
    const float* mlp_w2 = (const float*)d_in[17];
    const float* mlp_b2 = (const float*)d_in[18];
    const float* ro_w   = (const float*)d_in[19];
    const float* ro_b   = (const float*)d_in[20];

    const int Nn = in_sizes[0];
    const int Ee = in_sizes[1] / 2;
    const int Gg = out_size;

    float *t, *agg, *bf;
    uint4* Wf;
    cudaGetSymbolAddress((void**)&t,   g_t);
    cudaGetSymbolAddress((void**)&agg, g_agg);
    cudaGetSymbolAddress((void**)&Wf,  g_Wfrag);
    cudaGetSymbolAddress((void**)&bf,  g_bf);

    cudaFuncSetAttribute(gemm_dual, cudaFuncAttributeMaxDynamicSharedMemorySize, SM_TOTAL_G);
    cudaFuncSetAttribute(gemm_ro,   cudaFuncAttributeMaxDynamicSharedMemorySize, SM_TOTAL_G);

    const int gemm_grid = (Nn + 127) / 128;
    const int edge_grid = (Ee + 255) / 256;
    const int node_grid = (Nn + 1023) / 1024;
    const int warp_grid = ((Nn * 32) + 255) / 256;

    const size_t SLOT = (size_t)16 * 8 * 32;

    // fold pipeline (embed GEMM folded into a 100x128 table T0)
    fold_scale_kernel<<<6, H>>>(bn_g, bn_b, bn_m, bn_v, lin_w, lin_b,
                                mbn_g, mbn_b, mbn_m, mbn_v, mlp_w1, mlp_b1);
    fold_embed_kernel<<<100, H>>>(table);
    fold_mm_kernel<<<9, 256>>>(mlp_w2, mlp_b2, ro_w, ro_b);
    pack_kernel<<<40, H>>>();
    // output zero + CSR build
    zero_all_kernel<<<(Nn + 255) / 256, 256>>>((float*)d_out, Gg, Nn);
    hist_kernel<<<edge_grid, 256>>>(ei, Ee);
    scan_block_kernel<<<node_grid, 1024>>>(Nn);
    scan_bsum_kernel<<<1, 32>>>(node_grid);
    scan_final_kernel<<<node_grid, 1024>>>(Nn);
    fill_csr_kernel<<<edge_grid, 256>>>(ei, x, Ee);

    // layer 0: L1-resident gather from T0 + dual
    gather0_kernel<<<warp_grid, 256>>>(x, eps, agg, Nn);
    gemm_dual<<<gemm_grid, 256, SM_TOTAL_G>>>(
        agg, Wf + 1 * SLOT, bf + 1 * H, Wf + 2 * SLOT, bf + 2 * H, t, Nn);
    // layer 1
    gather_kernel<<<warp_grid, 256>>>(t, eps, 1, agg, Nn);
    gemm_dual<<<gemm_grid, 256, SM_TOTAL_G>>>(
        agg, Wf + 3 * SLOT, bf + 3 * H, Wf + 4 * SLOT, bf + 4 * H, t, Nn);
    // layer 2: gather + z-GEMM + folded readout
    gather_kernel<<<warp_grid, 256>>>(t, eps, 2, agg, Nn);
    gemm_ro<<<gemm_grid, 256, SM_TOTAL_G>>>(
        agg, Wf + 5 * SLOT, bf + 5 * H, batch, (float*)d_out, Nn);
}

// round 17
// speedup vs baseline: 1.0913x; 1.0612x over previous
#include <cuda_runtime.h>
#include <cuda_bf16.h>
#include <cstdint>

#define H 128
#define MAXN 50000
#define MAXE 800000
#define BN_EPS 1e-5f

// ---------------- device scratch ---------------------------------------------
__device__ float g_t[MAXN * H];
__device__ float g_agg[MAXN * H];
// Fragment slots: 1:Bz0 2:Cc0 3:Bz1 4:Cc1 5:Bz2
__device__ uint4 g_Wfrag[6 * 16 * 8 * 32];
__device__ float g_bf[6 * H];
// fp32 fold scratch
__device__ float g_scr[6 * H * H];
__device__ float g_SL[2 * H * H];
__device__ float g_bfold[2 * H];
__device__ float g_rov[H];
__device__ float g_roc[1];
__device__ float g_T0[100 * H];
// CSR scratch
__device__ int g_cnt[MAXN];
__device__ int g_tmp[MAXN];
__device__ int g_rowptr[MAXN + 1];
__device__ int g_csr_src[MAXE];
__device__ int g_csr_x[MAXE];
__device__ int g_bsum[64];

// ---------------- helpers -------------------------------------------------------
__device__ __forceinline__ uint32_t smem_addr_u32(const void* p) {
    uint32_t a;
    asm("{ .reg .u64 t; cvta.to.shared.u64 t, %1; cvt.u32.u64 %0, t; }" : "=r"(a) : "l"(p));
    return a;
}
__device__ __forceinline__ uint32_t pack_bf16x2(float a, float b) {
    uint32_t ua = (uint32_t)__bfloat16_as_ushort(__float2bfloat16_rn(a));
    uint32_t ub = (uint32_t)__bfloat16_as_ushort(__float2bfloat16_rn(b));
    return ua | (ub << 16);
}
__device__ __forceinline__ float bf16_rt(float x) {
    return __bfloat162float(__float2bfloat16_rn(x));
}
__device__ __forceinline__ void mma_bf16(float* d, const uint32_t* a,
                                         uint32_t b0, uint32_t b1) {
    asm volatile(
        "mma.sync.aligned.m16n8k16.row.col.f32.bf16.bf16.f32 "
        "{%0,%1,%2,%3}, {%4,%5,%6,%7}, {%8,%9}, {%0,%1,%2,%3};"
        : "+f"(d[0]), "+f"(d[1]), "+f"(d[2]), "+f"(d[3])
        : "r"(a[0]), "r"(a[1]), "r"(a[2]), "r"(a[3]), "r"(b0), "r"(b1));
}
__device__ __forceinline__ void ldmatrix_x4(uint32_t* r, uint32_t addr) {
    asm volatile("ldmatrix.sync.aligned.m8n8.x4.shared.b16 {%0,%1,%2,%3}, [%4];"
                 : "=r"(r[0]), "=r"(r[1]), "=r"(r[2]), "=r"(r[3]) : "r"(addr));
}

// ---------------- GEMM inner machinery (BM=128, grouped W loads) ------------------
#define AW 136   // bf16 per padded smem row

__device__ __forceinline__ void mma_pass(
    uint32_t aHiBase, uint32_t aLoBase, const uint4* __restrict__ Wtab,
    int J0, int lid, int R, float acc[2][8][4]) {
    const int lrow = (lid & 7) + ((lid >> 3) & 1) * 8;
    const int lcol = (lid >> 4) * 8;
#pragma unroll
    for (int katom = 0; katom < 8; katom++) {
        const int k0 = katom * 16;
        uint32_t ahi[2][4], alo[2][4];
#pragma unroll
        for (int m = 0; m < 2; m++) {
            uint32_t off = (uint32_t)((R + m * 16 + lrow) * AW + k0 + lcol) * 2;
            ldmatrix_x4(ahi[m], aHiBase + off);
            ldmatrix_x4(alo[m], aLoBase + off);
        }
#pragma unroll
        for (int grp = 0; grp < 2; grp++) {
            uint4 wf[4];
#pragma unroll
            for (int jj = 0; jj < 4; jj++)
                wf[jj] = __ldg(&Wtab[(((size_t)(J0 + grp * 4 + jj)) * 8 + katom) * 32 + lid]);
#pragma unroll
            for (int jj = 0; jj < 4; jj++)
                mma_bf16(acc[0][grp * 4 + jj], ahi[0], wf[jj].x, wf[jj].y);
#pragma unroll
            for (int jj = 0; jj < 4; jj++)
                mma_bf16(acc[1][grp * 4 + jj], ahi[1], wf[jj].x, wf[jj].y);
#pragma unroll
            for (int jj = 0; jj < 4; jj++)
                mma_bf16(acc[0][grp * 4 + jj], ahi[0], wf[jj].z, wf[jj].w);
#pragma unroll
            for (int jj = 0; jj < 4; jj++)
                mma_bf16(acc[1][grp * 4 + jj], ahi[1], wf[jj].z, wf[jj].w);
#pragma unroll
            for (int jj = 0; jj < 4; jj++)
                mma_bf16(acc[0][grp * 4 + jj], alo[0], wf[jj].x, wf[jj].y);
#pragma unroll
            for (int jj = 0; jj < 4; jj++)
                mma_bf16(acc[1][grp * 4 + jj], alo[1], wf[jj].x, wf[jj].y);
        }
    }
}

__device__ __forceinline__ void stage_tile(
    const float* __restrict__ A,
    __nv_bfloat16* sAhi, __nv_bfloat16* sAlo, int m0, int M, int tid) {
#pragma unroll
    for (int i = 0; i < 16; i++) {
        int idx = tid + i * 256;
        int row = idx >> 5;
        int c4  = idx & 31;
        int m = m0 + row;
        float4 v = make_float4(0.f, 0.f, 0.f, 0.f);
        if (m < M) v = *(const float4*)(A + (size_t)m * H + c4 * 4);
        float hx = bf16_rt(v.x), hy = bf16_rt(v.y);
        float hz = bf16_rt(v.z), hw = bf16_rt(v.w);
        uint2 hpack, lpack;
        hpack.x = pack_bf16x2(hx, hy);
        hpack.y = pack_bf16x2(hz, hw);
        lpack.x = pack_bf16x2(v.x - hx, v.y - hy);
        lpack.y = pack_bf16x2(v.z - hz, v.w - hw);
        *(uint2*)&sAhi[row * AW + c4 * 4] = hpack;
        *(uint2*)&sAlo[row * AW + c4 * 4] = lpack;
    }
}

// ---------------- small kernels -------------------------------------------------
__global__ void zero_all_kernel(float* out, int g, int n) {
    int i = blockIdx.x * blockDim.x + threadIdx.x;
    if (i < g) out[i] = 0.0f;
    if (i < n) { g_cnt[i] = 0; g_tmp[i] = 0; }
}
__global__ void hist_kernel(const int* __restrict__ ei, int Ee) {
    int e = blockIdx.x * blockDim.x + threadIdx.x;
    if (e >= Ee) return;
    atomicAdd(&g_cnt[__ldg(ei + Ee + e)], 1);
}
__global__ void scan_block_kernel(int n) {
    __shared__ int sh[1024];
    int gid = blockIdx.x * 1024 + threadIdx.x;
    int v = (gid < n) ? g_cnt[gid] : 0;
    sh[threadIdx.x] = v;
    __syncthreads();
    for (int off = 1; off < 1024; off <<= 1) {
        int t = (threadIdx.x >= off) ? sh[threadIdx.x - off] : 0;
        __syncthreads();
        sh[threadIdx.x] += t;
        __syncthreads();
    }
    if (gid < n) g_cnt[gid] = sh[threadIdx.x];
    if (threadIdx.x == 1023) g_bsum[blockIdx.x] = sh[1023];
}
// final: rowptr[gid+1] = cnt[gid] + exclusive-prefix(bsum up to my block)
__global__ void scan_final_kernel(int n) {
    __shared__ int base;
    if (threadIdx.x == 0) {
        int acc = 0;
        for (int i = 0; i < blockIdx.x; i++) acc += g_bsum[i];
        base = acc;
    }
    __syncthreads();
    int gid = blockIdx.x * 1024 + threadIdx.x;
    if (gid < n) g_rowptr[gid + 1] = g_cnt[gid] + base;
    if (gid == 0) g_rowptr[0] = 0;
}
__global__ void fill_csr_kernel(const int* __restrict__ ei,
                                const int* __restrict__ x, int Ee) {
    int e = blockIdx.x * blockDim.x + threadIdx.x;
    if (e >= Ee) return;
    int src = __ldg(ei + e);
    int dst = __ldg(ei + Ee + e);
    int pos = g_rowptr[dst] + atomicAdd(&g_tmp[dst], 1);
    g_csr_src[pos] = src;
    g_csr_x[pos] = __ldg(x + src);
}

// layer-0 gather: agg[n] = (1+eps)*T0[x[n]] + sum_{CSR[n]} T0[x[src]]
__global__ void gather0_kernel(const int* __restrict__ x,
                               const float* __restrict__ eps,
                               float* __restrict__ agg, int Nn) {
    int n = (blockIdx.x * blockDim.x + threadIdx.x) >> 5;
    int lane = threadIdx.x & 31;
    if (n >= Nn) return;
    float sc = 1.0f + __ldg(eps);
    const float* T0 = g_T0;
    float4 self = *(const float4*)(T0 + (size_t)__ldg(x + n) * H + lane * 4);
    float4 acc;
    acc.x = self.x * sc; acc.y = self.y * sc;
    acc.z = self.z * sc; acc.w = self.w * sc;
    int s = g_rowptr[n], e = g_rowptr[n + 1];
    int i = s;
    for (; i + 3 < e; i += 4) {
        int s0 = __ldg(g_csr_x + i);
        int s1 = __ldg(g_csr_x + i + 1);
        int s2 = __ldg(g_csr_x + i + 2);
        int s3 = __ldg(g_csr_x + i + 3);
        float4 v0 = *(const float4*)(T0 + (size_t)s0 * H + lane * 4);
        float4 v1 = *(const float4*)(T0 + (size_t)s1 * H + lane * 4);
        float4 v2 = *(const float4*)(T0 + (size_t)s2 * H + lane * 4);
        float4 v3 = *(const float4*)(T0 + (size_t)s3 * H + lane * 4);
        acc.x += (v0.x + v1.x) + (v2.x + v3.x);
        acc.y += (v0.y + v1.y) + (v2.y + v3.y);
        acc.z += (v0.z + v1.z) + (v2.z + v3.z);
        acc.w += (v0.w + v1.w) + (v2.w + v3.w);
    }
    for (; i < e; i++) {
        int s0 = __ldg(g_csr_x + i);
        float4 v0 = *(const float4*)(T0 + (size_t)s0 * H + lane * 4);
        acc.x += v0.x; acc.y += v0.y; acc.z += v0.z; acc.w += v0.w;
    }
    *(float4*)(agg + (size_t)n * H + lane * 4) = acc;
}

// layers 1,2 gather
__global__ void gather_kernel(const float* __restrict__ feat,
                              const float* __restrict__ eps, int layer,
                              float* __restrict__ agg, int Nn) {
    int n = (blockIdx.x * blockDim.x + threadIdx.x) >> 5;
    int lane = threadIdx.x & 31;
    if (n >= Nn) return;
    float sc = 1.0f + __ldg(eps + layer);
    float4 self = *(const float4*)(feat + (size_t)n * H + lane * 4);
    float4 acc;
    acc.x = self.x * sc; acc.y = self.y * sc;
    acc.z = self.z * sc; acc.w = self.w * sc;
    int s = g_rowptr[n], e = g_rowptr[n + 1];
    int i = s;
    for (; i + 3 < e; i += 4) {
        int s0 = __ldg(g_csr_src + i);
        int s1 = __ldg(g_csr_src + i + 1);
        int s2 = __ldg(g_csr_src + i + 2);
        int s3 = __ldg(g_csr_src + i + 3);
        float4 v0 = *(const float4*)(feat + (size_t)s0 * H + lane * 4);
        float4 v1 = *(const float4*)(feat + (size_t)s1 * H + lane * 4);
        float4 v2 = *(const float4*)(feat + (size_t)s2 * H + lane * 4);
        float4 v3 = *(const float4*)(feat + (size_t)s3 * H + lane * 4);
        acc.x += (v0.x + v1.x) + (v2.x + v3.x);
        acc.y += (v0.y + v1.y) + (v2.y + v3.y);
        acc.z += (v0.z + v1.z) + (v2.z + v3.z);
        acc.w += (v0.w + v1.w) + (v2.w + v3.w);
    }
    for (; i < e; i++) {
        int s0 = __ldg(g_csr_src + i);
        float4 v0 = *(const float4*)(feat + (size_t)s0 * H + lane * 4);
        acc.x += v0.x; acc.y += v0.y; acc.z += v0.z; acc.w += v0.w;
    }
    *(float4*)(agg + (size_t)n * H + lane * 4) = acc;
}

// ---------------- fold stage 1 ----------------------------------------------------
__global__ void fold_scale_kernel(
    const float* __restrict__ bn_g, const float* __restrict__ bn_b,
    const float* __restrict__ bn_m, const float* __restrict__ bn_v,
    const float* __restrict__ lin_w, const float* __restrict__ lin_b,
    const float* __restrict__ mbn_g, const float* __restrict__ mbn_b,
    const float* __restrict__ mbn_m, const float* __restrict__ mbn_v,
    const float* __restrict__ mlp_w1, const float* __restrict__ mlp_b1) {
    const int b = blockIdx.x;       // 0..5
    const int n = threadIdx.x;
    if (b < 3) {
        int l = b;
        __shared__ float ss[H], st[H];
        float s = bn_g[l * H + n] * rsqrtf(bn_v[l * H + n] + BN_EPS);
        ss[n] = s;
        st[n] = bn_b[l * H + n] - bn_m[l * H + n] * s;
        __syncthreads();
        const float* W = lin_w + (size_t)l * H * H;
        float* dst = (l == 0) ? g_scr : (g_SL + (size_t)(l - 1) * H * H);
        float bias = lin_b[l * H + n];
#pragma unroll 4
        for (int c = 0; c < H; c++) {
            float w = __ldg(W + c * H + n);
            dst[c * H + n] = ss[c] * w;
            bias += st[c] * w;
        }
        if (l == 0) g_bf[n] = bias;
        else        g_bfold[(l - 1) * H + n] = bias;
    } else {
        int l = b - 3;
        float sv = mbn_g[l * H + n] * rsqrtf(mbn_v[l * H + n] + BN_EPS);
        float tv = mbn_b[l * H + n] - mbn_m[l * H + n] * sv;
        const float* W = mlp_w1 + (size_t)l * H * H;
        float* dst = g_scr + (size_t)(1 + 2 * l) * H * H;
#pragma unroll 4
        for (int k = 0; k < H; k++)
            dst[k * H + n] = __ldg(W + k * H + n) * sv;
        g_bf[(1 + 2 * l) * H + n] = mlp_b1[l * H + n] * sv + tv;
    }
}

// ---------------- fold: T0 = relu(embed_table @ SL0 + bfold0) ---------------------
__global__ void fold_embed_kernel(const float* __restrict__ table) {
    const int v = blockIdx.x;
    const int n = threadIdx.x;
    __shared__ float row[H];
    row[n] = table[(size_t)v * H + n];
    __syncthreads();
    float acc = g_bf[n];
    const float* SL0 = g_scr;
#pragma unroll 4
    for (int c = 0; c < H; c++)
        acc += row[c] * SL0[c * H + n];
    g_T0[(size_t)v * H + n] = fmaxf(acc, 0.f);
}

// ---------------- fold stage 2: Cc_l = W2_l @ SL_{l+1}; readout fold --------------
__global__ void fold_mm_kernel(
    const float* __restrict__ mlp_w2, const float* __restrict__ mlp_b2,
    const float* __restrict__ ro_w, const float* __restrict__ ro_b) {
    const int b = blockIdx.x;       // 0..8
    if (b == 8) {
        __shared__ float ro[H];
        int t = threadIdx.x;
        if (t < H) ro[t] = ro_w[t];
        __syncthreads();
        if (t < H) {
            const float* W2 = mlp_w2 + (size_t)2 * H * H;
            float acc = 0.f;
            for (int j = 0; j < H; j++) acc += W2[t * H + j] * ro[j];
            g_rov[t] = acc;
        }
        if (t == 0) {
            const float* b2 = mlp_b2 + 2 * H;
            float acc = ro_b[0];
            for (int j = 0; j < H; j++) acc += b2[j] * ro[j];
            g_roc[0] = acc;
        }
        return;
    }
    const int l  = b >> 2;
    const int m0 = (b & 3) * 32;
    const float* W2 = mlp_w2 + (size_t)l * H * H;
    const float* SL = g_SL + (size_t)l * H * H;
    float* C = g_scr + (size_t)(2 + 2 * l) * H * H;

    __shared__ float sS[32][128];
    const int tm = threadIdx.x >> 4;
    const int tn = threadIdx.x & 15;
    float acc[2][8];
#pragma unroll
    for (int r = 0; r < 2; r++)
#pragma unroll
        for (int j = 0; j < 8; j++) acc[r][j] = 0.f;

    for (int kc = 0; kc < H; kc += 32) {
        for (int i = threadIdx.x; i < 32 * 128; i += 256)
            sS[i >> 7][i & 127] = SL[(size_t)(kc + (i >> 7)) * H + (i & 127)];
        __syncthreads();
        for (int kk = 0; kk < 32; kk++) {
            int k = kc + kk;
            float a0 = W2[(m0 + tm * 2)     * H + k];
            float a1 = W2[(m0 + tm * 2 + 1) * H + k];
#pragma unroll
            for (int j = 0; j < 8; j++) {
                float sv = sS[kk][tn * 8 + j];
                acc[0][j] += a0 * sv;
                acc[1][j] += a1 * sv;
            }
        }
        __syncthreads();
    }
#pragma unroll
    for (int r = 0; r < 2; r++)
#pragma unroll
        for (int j = 0; j < 8; j++)
            C[(size_t)(m0 + tm * 2 + r) * H + tn * 8 + j] = acc[r][j];

    if ((b & 3) == 0) {
        __syncthreads();
        int n = threadIdx.x;
        if (n < H) {
            const float* b2 = mlp_b2 + l * H;
            float a = g_bfold[l * H + n];
            for (int k = 0; k < H; k++) a += b2[k] * SL[(size_t)k * H + n];
            g_bf[(2 + 2 * l) * H + n] = a;
        }
    }
}

// ---------------- fold stage 3: pack fragments ------------------------------------
__global__ void pack_kernel() {
    const int slot  = (blockIdx.x >> 3) + 1;   // 1..5
    const int katom = blockIdx.x & 7;          // 0..7
    const int n = threadIdx.x;
    const float* W = g_scr + (size_t)slot * H * H;
    const int J = n >> 3;
    const int g = n & 7;
#pragma unroll
    for (int tg = 0; tg < 4; tg++) {
        int k0 = katom * 16 + tg * 2;
        float v00 = W[(k0)     * H + n];
        float v01 = W[(k0 + 1) * H + n];
        float v10 = W[(k0 + 8) * H + n];
        float v11 = W[(k0 + 9) * H + n];
        float h00 = bf16_rt(v00), h01 = bf16_rt(v01);
        float h10 = bf16_rt(v10), h11 = bf16_rt(v11);
        uint4 out;
        out.x = pack_bf16x2(h00, h01);
        out.y = pack_bf16x2(h10, h11);
        out.z = pack_bf16x2(v00 - h00, v01 - h01);
        out.w = pack_bf16x2(v10 - h10, v11 - h11);
        int lane = g * 4 + tg;
        g_Wfrag[(((size_t)slot * 16 + J) * 8 + katom) * 32 + lane] = out;
    }
}

// ---------------- smem layout (BM=128) ---------------------------------------------
static constexpr int SM_AHI   = 0;
static constexpr int SM_ALO   = 128 * AW * 2;
static constexpr int SM_BIAS1 = 2 * 128 * AW * 2;
static constexpr int SM_BIAS2 = SM_BIAS1 + 512;
static constexpr int SM_RO    = SM_BIAS2 + 512;
static constexpr int SM_TOTAL_G = SM_RO + 512;

// ---------------- dual: t' = relu( relu(agg@Bz+bz) @ Cc + bc ) --------------------
__global__ void __launch_bounds__(256, 2)
gemm_dual(const float* __restrict__ A,
          const uint4* __restrict__ Wf1, const float* __restrict__ b1,
          const uint4* __restrict__ Wf2, const float* __restrict__ b2,
          float* __restrict__ Cout, int M) {
    extern __shared__ char smem[];
    __nv_bfloat16* sAhi = (__nv_bfloat16*)(smem + SM_AHI);
    __nv_bfloat16* sAlo = (__nv_bfloat16*)(smem + SM_ALO);
    float* sBias1 = (float*)(smem + SM_BIAS1);
    float* sBias2 = (float*)(smem + SM_BIAS2);

    const int tid = threadIdx.x;
    const int wid = tid >> 5, lid = tid & 31;
    const int m0 = blockIdx.x * 128;
    const int J0 = (wid >> 2) * 8;
    const int R = (wid & 3) * 32;
    const uint32_t aHiBase = smem_addr_u32(sAhi);
    const uint32_t aLoBase = smem_addr_u32(sAlo);

    if (tid < H) {
        sBias1[tid] = b1[tid];
        sBias2[tid] = b2[tid];
    }
    stage_tile(A, sAhi, sAlo, m0, M, tid);
    __syncthreads();

    float acc[2][8][4];
#pragma unroll
    for (int m = 0; m < 2; m++)
#pragma unroll
        for (int j = 0; j < 8; j++)
#pragma unroll
            for (int r = 0; r < 4; r++) acc[m][j][r] = 0.0f;

    mma_pass(aHiBase, aLoBase, Wf1, J0, lid, R, acc);

    const int cb = (wid >> 2) * 64;
    const int g = lid >> 2, tg = lid & 3;

    __syncthreads();
#pragma unroll
    for (int m = 0; m < 2; m++)
#pragma unroll
        for (int rh = 0; rh < 2; rh++) {
            int row = R + m * 16 + rh * 8 + g;
#pragma unroll
            for (int j = 0; j < 8; j++) {
                int c = cb + j * 8 + tg * 2;
                float zx = fmaxf(acc[m][j][rh * 2 + 0] + sBias1[c], 0.f);
                float zy = fmaxf(acc[m][j][rh * 2 + 1] + sBias1[c + 1], 0.f);
                float hx = bf16_rt(zx), hy = bf16_rt(zy);
                *(uint32_t*)&sAhi[row * AW + c] = pack_bf16x2(hx, hy);
                *(uint32_t*)&sAlo[row * AW + c] = pack_bf16x2(zx - hx, zy - hy);
            }
        }
    __syncthreads();

#pragma unroll
    for (int m = 0; m < 2; m++)
#pragma unroll
        for (int j = 0; j < 8; j++)
#pragma unroll
            for (int r = 0; r < 4; r++) acc[m][j][r] = 0.0f;

    mma_pass(aHiBase, aLoBase, Wf2, J0, lid, R, acc);

    const int r0 = m0 + R;
#pragma unroll
    for (int m = 0; m < 2; m++)
#pragma unroll
        for (int rh = 0; rh < 2; rh++) {
            int row = r0 + m * 16 + rh * 8 + g;
            if (row < M) {
#pragma unroll
                for (int j = 0; j < 8; j++) {
                    int c = cb + j * 8 + tg * 2;
                    float2 o;
                    o.x = fmaxf(acc[m][j][rh * 2 + 0] + sBias2[c], 0.f);
                    o.y = fmaxf(acc[m][j][rh * 2 + 1] + sBias2[c + 1], 0.f);
                    *(float2*)(Cout + (size_t)row * H + c) = o;
                }
            }
        }
}

// ---------------- layer-2: z = relu(agg@Bz2+bz2); out += z.v + c -----------------
__global__ void __launch_bounds__(256, 2)
gemm_ro(const float* __restrict__ A,
        const uint4* __restrict__ Wf, const float* __restrict__ bias,
        const int* __restrict__ batch, float* __restrict__ gout, int M) {
    extern __shared__ char smem[];
    __nv_bfloat16* sAhi = (__nv_bfloat16*)(smem + SM_AHI);
    __nv_bfloat16* sAlo = (__nv_bfloat16*)(smem + SM_ALO);
    float* sBias = (float*)(smem + SM_BIAS1);
    float* sRo   = (float*)(smem + SM_RO);

    const int tid = threadIdx.x;
    const int wid = tid >> 5, lid = tid & 31;
    const int m0 = blockIdx.x * 128;
    const int J0 = (wid >> 2) * 8;
    const int R = (wid & 3) * 32;

    if (tid < H) {
        sBias[tid] = bias[tid];
        sRo[tid] = g_rov[tid];
    }
    stage_tile(A, sAhi, sAlo, m0, M, tid);
    __syncthreads();

    float acc[2][8][4];
#pragma unroll
    for (int m = 0; m < 2; m++)
#pragma unroll
        for (int j = 0; j < 8; j++)
#pragma unroll
            for (int r = 0; r < 4; r++) acc[m][j][r] = 0.0f;

    mma_pass(smem_addr_u32(sAhi), smem_addr_u32(sAlo), Wf, J0, lid, R, acc);

    const int r0 = m0 + R;
    const int cb = (wid >> 2) * 64;
    const int g = lid >> 2, tg = lid & 3;
    const float roc = g_roc[0];
    float dots[4] = {0.f, 0.f, 0.f, 0.f};
#pragma unroll
    for (int m = 0; m < 2; m++)
#pragma unroll
        for (int rh = 0; rh < 2; rh++) {
            int row = r0 + m * 16 + rh * 8 + g;
            if (row < M) {
                float dv = 0.f;
#pragma unroll
                for (int j = 0; j < 8; j++) {
                    int c = cb + j * 8 + tg * 2;
                    float zx = fmaxf(acc[m][j][rh * 2 + 0] + sBias[c], 0.f);
                    float zy = fmaxf(acc[m][j][rh * 2 + 1] + sBias[c + 1], 0.f);
                    dv += zx * sRo[c] + zy * sRo[c + 1];
                }
                dots[m * 2 + rh] = dv;
            }
        }
#pragma unroll
    for (int s = 0; s < 4; s++) {
        float v = dots[s];
        v += __shfl_xor_sync(0xffffffff, v, 1);
        v += __shfl_xor_sync(0xffffffff, v, 2);
        int row = r0 + (s >> 1) * 16 + (s & 1) * 8 + g;
        if (tg == 0 && row < M) {
            if (cb == 0) v += roc;
            atomicAdd(gout + __ldg(batch + row), v);
        }
    }
}

// ---------------- launcher ------------------------------------------------------
extern "C" void kernel_launch(void* const* d_in, const int* in_sizes, int n_in,
                              void* d_out, int out_size) {
    const int*   x      = (const int*)d_in[0];
    const int*   ei     = (const int*)d_in[1];
    const int*   batch  = (const int*)d_in[2];
    const float* table  = (const float*)d_in[3];
    const float* bn_g   = (const float*)d_in[4];
    const float* bn_b   = (const float*)d_in[5];
    const float* bn_m   = (const float*)d_in[6];
    const float* bn_v   = (const float*)d_in[7];
    const float* lin_w  = (const float*)d_in[8];
    const float* lin_b  = (const float*)d_in[9];
    const float* eps    = (const float*)d_in[10];
    const float* mlp_w1 = (const float*)d_in[11];
    const float* mlp_b1 = (const float*)d_in[12];
    const float* mbn_g  = (const float*)d_in[13];
    const float* mbn_b  = (const float*)d_in[14];
    const float* mbn_m  = (const float*)d_in[15];
    const float* mbn_v  = (const float*)d_in[16];
    const float* mlp_w2 = (const float*)d_in[17];
    const float* mlp_b2 = (const float*)d_in[18];
    const float* ro_w   = (const float*)d_in[19];
    const float* ro_b   = (const float*)d_in[20];

    const int Nn = in_sizes[0];
    const int Ee = in_sizes[1] / 2;
    const int Gg = out_size;

    float *t, *agg, *bf;
    uint4* Wf;
    cudaGetSymbolAddress((void**)&t,   g_t);
    cudaGetSymbolAddress((void**)&agg, g_agg);
    cudaGetSymbolAddress((void**)&Wf,  g_Wfrag);
    cudaGetSymbolAddress((void**)&bf,  g_bf);

    cudaFuncSetAttribute(gemm_dual, cudaFuncAttributeMaxDynamicSharedMemorySize, SM_TOTAL_G);
    cudaFuncSetAttribute(gemm_ro,   cudaFuncAttributeMaxDynamicSharedMemorySize, SM_TOTAL_G);

    const int gemm_grid = (Nn + 127) / 128;
    const int edge_grid = (Ee + 255) / 256;
    const int node_grid = (Nn + 1023) / 1024;
    const int warp_grid = ((Nn * 32) + 255) / 256;

    const size_t SLOT = (size_t)16 * 8 * 32;

    // Fork a side stream so the weight-fold pipeline runs concurrently with the
    // CSR build inside the captured graph (host stream/event objects only; no
    // device allocation).
    cudaStream_t s1;
    cudaStreamCreateWithFlags(&s1, cudaStreamNonBlocking);
    cudaEvent_t evF, evJ;
    cudaEventCreateWithFlags(&evF, cudaEventDisableTiming);
    cudaEventCreateWithFlags(&evJ, cudaEventDisableTiming);

    cudaEventRecord(evF, 0);
    cudaStreamWaitEvent(s1, evF, 0);

    // side stream: weight folds (independent of the graph topology work)
    fold_scale_kernel<<<6, H, 0, s1>>>(bn_g, bn_b, bn_m, bn_v, lin_w, lin_b,
                                       mbn_g, mbn_b, mbn_m, mbn_v, mlp_w1, mlp_b1);
    fold_embed_kernel<<<100, H, 0, s1>>>(table);
    fold_mm_kernel<<<9, 256, 0, s1>>>(mlp_w2, mlp_b2, ro_w, ro_b);
    pack_kernel<<<40, H, 0, s1>>>();
    cudaEventRecord(evJ, s1);

    // main stream: output zero + CSR build
    zero_all_kernel<<<(Nn + 255) / 256, 256>>>((float*)d_out, Gg, Nn);
    hist_kernel<<<edge_grid, 256>>>(ei, Ee);
    scan_block_kernel<<<node_grid, 1024>>>(Nn);
    scan_final_kernel<<<node_grid, 1024>>>(Nn);
    fill_csr_kernel<<<edge_grid, 256>>>(ei, x, Ee);

    // join: layers need both CSR and folded weights/T0
    cudaStreamWaitEvent(0, evJ, 0);

    // layer 0: L1-resident gather from T0 + dual
    gather0_kernel<<<warp_grid, 256>>>(x, eps, agg, Nn);
    gemm_dual<<<gemm_grid, 256, SM_TOTAL_G>>>(
        agg, Wf + 1 * SLOT, bf + 1 * H, Wf + 2 * SLOT, bf + 2 * H, t, Nn);
    // layer 1
    gather_kernel<<<warp_grid, 256>>>(t, eps, 1, agg, Nn);
    gemm_dual<<<gemm_grid, 256, SM_TOTAL_G>>>(
        agg, Wf + 3 * SLOT, bf + 3 * H, Wf + 4 * SLOT, bf + 4 * H, t, Nn);
    // layer 2: gather + z-GEMM + folded readout
    gather_kernel<<<warp_grid, 256>>>(t, eps, 2, agg, Nn);
    gemm_ro<<<gemm_grid, 256, SM_TOTAL_G>>>(
        agg, Wf + 5 * SLOT, bf + 5 * H, batch, (float*)d_out, Nn);
}